// round 3
// baseline (speedup 1.0000x reference)
#include <cuda_runtime.h>
#include <math.h>

#define BB 64
#define NN 16384
#define MM 128
#define CC 1024
#define EPSV 1e-16f
#define GRP 4
#define NGRP (BB / GRP)

// ---- scratch (device globals; no allocation allowed) ----
__device__ float g_S[BB * NN];          // 4 MB: exp(beta*(sim-1)) values
__device__ float g_k[BB * MM];
__device__ float g_kn[BB];
__device__ float g_beta[BB], g_gate[BB], g_gamma[BB];
__device__ float g_shift[BB][3];
__device__ float g_Z[BB];               // softmax denominator (shift = beta)
__device__ float g_WZ[BB];              // sharpen denominator

__device__ __forceinline__ float softplus_f(float x) {
    return (x > 20.f) ? x : log1pf(expf(x));
}

// ---- 1. init accumulators + zero read_vec output region ----
__global__ void k_init(float* __restrict__ out_read) {
    int i = blockIdx.x * blockDim.x + threadIdx.x;
    if (i < BB) { g_Z[i] = 0.f; g_WZ[i] = 0.f; }
    if (i < BB * MM) out_read[i] = 0.f;
}

// ---- 2. projections: k=tanh(ctrl@Wk+bk), beta/gate/gamma/shift heads ----
__global__ void k_proj(const float* __restrict__ ctrl,
                       const float* __restrict__ key_w, const float* __restrict__ key_b,
                       const float* __restrict__ beta_w, const float* __restrict__ beta_b,
                       const float* __restrict__ gate_w, const float* __restrict__ gate_b,
                       const float* __restrict__ shift_w, const float* __restrict__ shift_b,
                       const float* __restrict__ gamma_w, const float* __restrict__ gamma_b) {
    __shared__ float sc[CC];
    __shared__ float red[MM];
    __shared__ float r6[6][MM];
    int b = blockIdx.x, t = threadIdx.x;
    for (int i = t; i < CC; i += MM) sc[i] = ctrl[b * CC + i];
    __syncthreads();

    // key column t
    float acc = 0.f;
    #pragma unroll 8
    for (int c = 0; c < CC; c++) acc += sc[c] * key_w[c * MM + t];
    float kt = tanhf(acc + key_b[t]);
    g_k[b * MM + t] = kt;

    red[t] = kt * kt;
    __syncthreads();
    for (int s = 64; s > 0; s >>= 1) {
        if (t < s) red[t] += red[t + s];
        __syncthreads();
    }
    if (t == 0) g_kn[b] = sqrtf(red[0]);

    // 6 scalar dots
    float a0 = 0, a1 = 0, a2 = 0, s0 = 0, s1 = 0, s2 = 0;
    for (int c = t; c < CC; c += MM) {
        float x = sc[c];
        a0 += x * beta_w[c];
        a1 += x * gate_w[c];
        a2 += x * gamma_w[c];
        s0 += x * shift_w[c * 3 + 0];
        s1 += x * shift_w[c * 3 + 1];
        s2 += x * shift_w[c * 3 + 2];
    }
    r6[0][t] = a0; r6[1][t] = a1; r6[2][t] = a2;
    r6[3][t] = s0; r6[4][t] = s1; r6[5][t] = s2;
    __syncthreads();
    for (int s = 64; s > 0; s >>= 1) {
        if (t < s)
            #pragma unroll
            for (int j = 0; j < 6; j++) r6[j][t] += r6[j][t + s];
        __syncthreads();
    }
    if (t == 0) {
        g_beta[b]  = softplus_f(r6[0][0] + beta_b[0]);
        g_gate[b]  = 1.f / (1.f + expf(-(r6[1][0] + gate_b[0])));
        g_gamma[b] = 1.f + softplus_f(r6[2][0] + gamma_b[0]);
        float v0 = r6[3][0] + shift_b[0];
        float v1 = r6[4][0] + shift_b[1];
        float v2 = r6[5][0] + shift_b[2];
        float mx = fmaxf(v0, fmaxf(v1, v2));
        float e0 = expf(v0 - mx), e1 = expf(v1 - mx), e2 = expf(v2 - mx);
        float inv = 1.f / (e0 + e1 + e2);
        g_shift[b][0] = e0 * inv;
        g_shift[b][1] = e1 * inv;
        g_shift[b][2] = e2 * inv;
    }
}

// ---- 3. gated interp + circular shift + sharpen power; write wp to d_out ----
__global__ void __launch_bounds__(256) k_w(const float* __restrict__ pw,
                                           float* __restrict__ out_w, int b0) {
    __shared__ float red[256];
    int b = b0 + blockIdx.y, t = threadIdx.x;
    float gate = g_gate[b], og = 1.f - gate;
    float invZ = 1.f / g_Z[b];
    float s0 = g_shift[b][0], s1 = g_shift[b][1], s2 = g_shift[b][2];
    float gamma = g_gamma[b];
    const float* Sb = g_S + (size_t)b * NN;
    const float* pwb = pw + (size_t)b * NN;
    int n0 = blockIdx.x * 1024 + t * 4;

    float w[6];
    #pragma unroll
    for (int j = 0; j < 6; j++) {
        int nn = (n0 - 1 + j) & (NN - 1);
        w[j] = gate * Sb[nn] * invZ + og * pwb[nn];
    }
    float lsum = 0.f;
    #pragma unroll
    for (int j = 0; j < 4; j++) {
        float ws = s0 * w[j] + s1 * w[j + 1] + s2 * w[j + 2];
        float wp = __powf(ws, gamma);
        out_w[(size_t)b * NN + n0 + j] = wp;
        lsum += wp;
    }
    red[t] = lsum;
    __syncthreads();
    for (int s = 128; s > 0; s >>= 1) {
        if (t < s) red[t] += red[t + s];
        __syncthreads();
    }
    if (t == 0) atomicAdd(&g_WZ[b], red[0]);
}

// ---- 4. combined kernel: read(group g) blocks first (L2-hot), then
//         sim(group g+1) blocks streaming from DRAM, in ONE launch ----
__global__ void __launch_bounds__(256) k_comb(const float* __restrict__ mem,
                                              float* __restrict__ out,
                                              int b_read0, int nb_read,
                                              int b_sim0, int nb_sim) {
    __shared__ float sh[256];
    int bx = blockIdx.x;
    int rblocks = nb_read * 64;

    if (bx < rblocks) {
        // ---- READ role: normalize weights in place + weighted read ----
        int t = threadIdx.x;
        int b = b_read0 + (bx >> 6);
        int base = (bx & 63) * 256;
        float inv = 1.f / (g_WZ[b] + EPSV);
        float* wout = out + (size_t)b * NN;
        float w = wout[base + t] * inv;
        wout[base + t] = w;
        sh[t] = w;
        __syncthreads();

        int col = t & 127, h = t >> 7;
        const float* mb = mem + ((size_t)b * NN + base + h * 128) * MM + col;
        const float* swp = sh + h * 128;
        float a0 = 0.f, a1 = 0.f, a2 = 0.f, a3 = 0.f;
        #pragma unroll 4
        for (int i = 0; i < 128; i += 4) {
            a0 += swp[i]     * mb[(size_t)(i)     * MM];
            a1 += swp[i + 1] * mb[(size_t)(i + 1) * MM];
            a2 += swp[i + 2] * mb[(size_t)(i + 2) * MM];
            a3 += swp[i + 3] * mb[(size_t)(i + 3) * MM];
        }
        atomicAdd(&out[(size_t)BB * NN + b * MM + col], (a0 + a1) + (a2 + a3));
    } else {
        // ---- SIM role: beta*cosine-sim -> exp(beta*(sim-1)), accumulate Z ----
        bx -= rblocks;
        int tid = threadIdx.x, warp = tid >> 5, lane = tid & 31;
        int b = b_sim0 + (bx >> 6);
        int base = (bx & 63) * 256;
        if (tid < MM) sh[tid] = g_k[b * MM + tid];
        __syncthreads();
        float k0 = sh[lane * 4 + 0], k1 = sh[lane * 4 + 1];
        float k2 = sh[lane * 4 + 2], k3 = sh[lane * 4 + 3];
        float beta = g_beta[b], kn = g_kn[b];
        float zsum = 0.f;
        const float4* mp = (const float4*)(mem + (size_t)b * NN * MM);

        #pragma unroll 4
        for (int i = 0; i < 32; i++) {
            int n = base + i * 8 + warp;
            float4 v = mp[(size_t)n * 32 + lane];
            float dot = k0 * v.x + k1 * v.y + k2 * v.z + k3 * v.w;
            float nrm = v.x * v.x + v.y * v.y + v.z * v.z + v.w * v.w;
            #pragma unroll
            for (int off = 16; off > 0; off >>= 1) {
                dot += __shfl_down_sync(0xffffffffu, dot, off);
                nrm += __shfl_down_sync(0xffffffffu, nrm, off);
            }
            if (lane == 0) {
                float s = beta * dot / (kn * sqrtf(nrm) + EPSV);
                float e = __expf(s - beta);   // shift by beta >= max(beta*sim)
                g_S[b * NN + n] = e;
                zsum += e;
            }
        }
        if (lane == 0) atomicAdd(&g_Z[b], zsum);
    }
}

extern "C" void kernel_launch(void* const* d_in, const int* in_sizes, int n_in,
                              void* d_out, int out_size) {
    const float* ctrl    = (const float*)d_in[0];
    const float* pw      = (const float*)d_in[1];
    const float* mem     = (const float*)d_in[2];
    const float* key_w   = (const float*)d_in[3];
    const float* key_b   = (const float*)d_in[4];
    const float* beta_w  = (const float*)d_in[5];
    const float* beta_b  = (const float*)d_in[6];
    const float* gate_w  = (const float*)d_in[7];
    const float* gate_b  = (const float*)d_in[8];
    const float* shift_w = (const float*)d_in[9];
    const float* shift_b = (const float*)d_in[10];
    const float* gamma_w = (const float*)d_in[11];
    const float* gamma_b = (const float*)d_in[12];
    // d_in[13..16] = erase_w/b, add_w/b — unused by the output, skipped.
    float* out = (float*)d_out;
    float* out_read = out + (size_t)BB * NN;

    k_init<<<32, 256>>>(out_read);
    k_proj<<<BB, MM>>>(ctrl, key_w, key_b, beta_w, beta_b, gate_w, gate_b,
                       shift_w, shift_b, gamma_w, gamma_b);

    // prologue: sim for group 0 only
    k_comb<<<64 * GRP, 256>>>(mem, out, 0, 0, 0, GRP);

    for (int g = 0; g < NGRP; g++) {
        k_w<<<dim3(NN / 1024, GRP), 256>>>(pw, out, g * GRP);
        int nbs = (g + 1 < NGRP) ? GRP : 0;
        k_comb<<<64 * (GRP + nbs), 256>>>(mem, out,
                                          g * GRP, GRP,
                                          (g + 1) * GRP, nbs);
    }
}

// round 5
// speedup vs baseline: 2.6849x; 2.6849x over previous
#include <cuda_runtime.h>
#include <math.h>

#define BB 64
#define NN 16384
#define MM 128
#define CC 1024
#define EPSV 1e-16f

// ---- scratch (device globals; no allocation allowed) ----
__device__ float g_S[BB * NN];          // 4 MB: exp(beta*(sim-1))
__device__ float g_k[BB * MM];
__device__ float g_kn[BB];
__device__ float g_beta[BB], g_gate[BB], g_gamma[BB];
__device__ float g_shift[BB][3];
__device__ float g_Z[BB];               // softmax denominator (shift = beta)
__device__ float g_WZ[BB];              // sharpen denominator

__device__ __forceinline__ float softplus_f(float x) {
    return (x > 20.f) ? x : log1pf(expf(x));
}

// ---- 1. init accumulators + zero read_vec output region ----
__global__ void k_init(float* __restrict__ out_read) {
    int i = blockIdx.x * blockDim.x + threadIdx.x;
    if (i < BB) { g_Z[i] = 0.f; g_WZ[i] = 0.f; }
    if (i < BB * MM) out_read[i] = 0.f;
}

// ---- 2. projections (512 threads/block, one block per batch) ----
__global__ void __launch_bounds__(512) k_proj(
        const float* __restrict__ ctrl,
        const float* __restrict__ key_w, const float* __restrict__ key_b,
        const float* __restrict__ beta_w, const float* __restrict__ beta_b,
        const float* __restrict__ gate_w, const float* __restrict__ gate_b,
        const float* __restrict__ shift_w, const float* __restrict__ shift_b,
        const float* __restrict__ gamma_w, const float* __restrict__ gamma_b) {
    __shared__ float sc[CC];
    __shared__ float kred[4][MM];
    __shared__ float r6[6][16];
    __shared__ float red[MM];
    int b = blockIdx.x, t = threadIdx.x;
    int lane = t & 31, wid = t >> 5;

    for (int i = t; i < CC; i += 512) sc[i] = ctrl[b * CC + i];
    __syncthreads();

    // key column (t&127), C-quarter (t>>7)
    int q = t >> 7, col = t & 127;
    float acc = 0.f;
    int c0 = q * 256;
    #pragma unroll 8
    for (int c = c0; c < c0 + 256; c++) acc += sc[c] * key_w[c * MM + col];
    kred[q][col] = acc;

    // 6 scalar dots: 2 elements per thread, warp-reduce
    float a0 = 0, a1 = 0, a2 = 0, s0 = 0, s1 = 0, s2 = 0;
    for (int c = t; c < CC; c += 512) {
        float x = sc[c];
        a0 += x * beta_w[c];
        a1 += x * gate_w[c];
        a2 += x * gamma_w[c];
        s0 += x * shift_w[c * 3 + 0];
        s1 += x * shift_w[c * 3 + 1];
        s2 += x * shift_w[c * 3 + 2];
    }
    #pragma unroll
    for (int off = 16; off > 0; off >>= 1) {
        a0 += __shfl_down_sync(0xffffffffu, a0, off);
        a1 += __shfl_down_sync(0xffffffffu, a1, off);
        a2 += __shfl_down_sync(0xffffffffu, a2, off);
        s0 += __shfl_down_sync(0xffffffffu, s0, off);
        s1 += __shfl_down_sync(0xffffffffu, s1, off);
        s2 += __shfl_down_sync(0xffffffffu, s2, off);
    }
    if (lane == 0) {
        r6[0][wid] = a0; r6[1][wid] = a1; r6[2][wid] = a2;
        r6[3][wid] = s0; r6[4][wid] = s1; r6[5][wid] = s2;
    }
    __syncthreads();

    float kt = 0.f;
    if (t < MM) {
        kt = tanhf(kred[0][t] + kred[1][t] + kred[2][t] + kred[3][t] + key_b[t]);
        g_k[b * MM + t] = kt;
        red[t] = kt * kt;
    }
    __syncthreads();
    for (int s = 64; s > 0; s >>= 1) {
        if (t < s) red[t] += red[t + s];
        __syncthreads();
    }
    if (t == 0) {
        g_kn[b] = sqrtf(red[0]);
        float v[6];
        #pragma unroll
        for (int j = 0; j < 6; j++) {
            float sum = 0.f;
            #pragma unroll
            for (int w = 0; w < 16; w++) sum += r6[j][w];
            v[j] = sum;
        }
        g_beta[b]  = softplus_f(v[0] + beta_b[0]);
        g_gate[b]  = 1.f / (1.f + expf(-(v[1] + gate_b[0])));
        g_gamma[b] = 1.f + softplus_f(v[2] + gamma_b[0]);
        float v0 = v[3] + shift_b[0];
        float v1 = v[4] + shift_b[1];
        float v2 = v[5] + shift_b[2];
        float mx = fmaxf(v0, fmaxf(v1, v2));
        float e0 = expf(v0 - mx), e1 = expf(v1 - mx), e2 = expf(v2 - mx);
        float inv = 1.f / (e0 + e1 + e2);
        g_shift[b][0] = e0 * inv;
        g_shift[b][1] = e1 * inv;
        g_shift[b][2] = e2 * inv;
    }
}

// ---- 3. pass 1 over memory: exp(beta*(sim-1)) + Z; 8 lanes/row, 4 rows/iter ----
__global__ void __launch_bounds__(256) k_sim(const float* __restrict__ mem) {
    int b = blockIdx.y;
    int tid = threadIdx.x, warp = tid >> 5, lane = tid & 31;
    int sub = lane & 7, rg = lane >> 3;
    __shared__ float sk[MM];
    if (tid < MM) sk[tid] = g_k[b * MM + tid];
    __syncthreads();
    const float4* skp = (const float4*)sk;
    float4 kq0 = skp[sub], kq1 = skp[sub + 8], kq2 = skp[sub + 16], kq3 = skp[sub + 24];
    float beta = g_beta[b], kn = g_kn[b];
    float zsum = 0.f;
    int base = blockIdx.x * 256 + warp * 32;
    const float4* mp = (const float4*)(mem + (size_t)b * NN * MM);

    #pragma unroll 2
    for (int j = 0; j < 8; j++) {
        int row = base + j * 4 + rg;
        const float4* rp = mp + (size_t)row * 32;
        float4 v0 = rp[sub], v1 = rp[sub + 8], v2 = rp[sub + 16], v3 = rp[sub + 24];
        float dot = v0.x * kq0.x + v0.y * kq0.y + v0.z * kq0.z + v0.w * kq0.w
                  + v1.x * kq1.x + v1.y * kq1.y + v1.z * kq1.z + v1.w * kq1.w
                  + v2.x * kq2.x + v2.y * kq2.y + v2.z * kq2.z + v2.w * kq2.w
                  + v3.x * kq3.x + v3.y * kq3.y + v3.z * kq3.z + v3.w * kq3.w;
        float nrm = v0.x * v0.x + v0.y * v0.y + v0.z * v0.z + v0.w * v0.w
                  + v1.x * v1.x + v1.y * v1.y + v1.z * v1.z + v1.w * v1.w
                  + v2.x * v2.x + v2.y * v2.y + v2.z * v2.z + v2.w * v2.w
                  + v3.x * v3.x + v3.y * v3.y + v3.z * v3.z + v3.w * v3.w;
        #pragma unroll
        for (int off = 4; off > 0; off >>= 1) {
            dot += __shfl_down_sync(0xffffffffu, dot, off);
            nrm += __shfl_down_sync(0xffffffffu, nrm, off);
        }
        if (sub == 0) {
            float s = beta * dot / (kn * sqrtf(nrm) + EPSV);
            float e = __expf(s - beta);
            g_S[b * NN + row] = e;
            zsum += e;
        }
    }
    zsum += __shfl_down_sync(0xffffffffu, zsum, 16);
    zsum += __shfl_down_sync(0xffffffffu, zsum, 8);
    if (lane == 0) atomicAdd(&g_Z[b], zsum);
}

// ---- 4. gated interp + circular shift + sharpen power; write wp to d_out ----
__global__ void __launch_bounds__(256) k_w(const float* __restrict__ pw,
                                           float* __restrict__ out_w) {
    __shared__ float red[256];
    int b = blockIdx.y, t = threadIdx.x;
    float gate = g_gate[b], og = 1.f - gate;
    float invZ = 1.f / g_Z[b];
    float s0 = g_shift[b][0], s1 = g_shift[b][1], s2 = g_shift[b][2];
    float gamma = g_gamma[b];
    const float* Sb = g_S + (size_t)b * NN;
    const float* pwb = pw + (size_t)b * NN;
    int n0 = blockIdx.x * 1024 + t * 4;

    float w[6];
    #pragma unroll
    for (int j = 0; j < 6; j++) {
        int nn = (n0 - 1 + j) & (NN - 1);
        w[j] = gate * Sb[nn] * invZ + og * pwb[nn];
    }
    float lsum = 0.f;
    #pragma unroll
    for (int j = 0; j < 4; j++) {
        float ws = s0 * w[j] + s1 * w[j + 1] + s2 * w[j + 2];
        float wp = __powf(ws, gamma);
        out_w[(size_t)b * NN + n0 + j] = wp;
        lsum += wp;
    }
    red[t] = lsum;
    __syncthreads();
    for (int s = 128; s > 0; s >>= 1) {
        if (t < s) red[t] += red[t + s];
        __syncthreads();
    }
    if (t == 0) atomicAdd(&g_WZ[b], red[0]);
}

// ---- 5. pass 2: normalize weights in place + weighted read (float4 accs) ----
__global__ void __launch_bounds__(256) k_read(const float* __restrict__ mem,
                                              float* __restrict__ out) {
    __shared__ float sw[256];
    __shared__ float4 sacc[256];
    int b = blockIdx.y, t = threadIdx.x, warp = t >> 5, lane = t & 31;
    int base = blockIdx.x * 256;
    float inv = 1.f / (g_WZ[b] + EPSV);
    float* wout = out + (size_t)b * NN;
    float w = wout[base + t] * inv;
    wout[base + t] = w;
    sw[t] = w;
    __syncthreads();

    // warp handles rows base+warp*32 .. +31; lane owns cols 4*lane..4*lane+3
    const float4* mp = (const float4*)(mem + ((size_t)b * NN + base + warp * 32) * MM);
    const float* swp = sw + warp * 32;
    float4 acc = make_float4(0.f, 0.f, 0.f, 0.f);
    #pragma unroll 4
    for (int i = 0; i < 32; i++) {
        float4 v = mp[(size_t)i * 32 + lane];
        float wi = swp[i];
        acc.x += wi * v.x; acc.y += wi * v.y;
        acc.z += wi * v.z; acc.w += wi * v.w;
    }
    sacc[t] = acc;
    __syncthreads();

    if (t < 32) {
        float4 s = sacc[t];
        #pragma unroll
        for (int w8 = 1; w8 < 8; w8++) {
            float4 o = sacc[w8 * 32 + t];
            s.x += o.x; s.y += o.y; s.z += o.z; s.w += o.w;
        }
        float* rd = out + (size_t)BB * NN + b * MM + t * 4;
        atomicAdd(rd + 0, s.x);
        atomicAdd(rd + 1, s.y);
        atomicAdd(rd + 2, s.z);
        atomicAdd(rd + 3, s.w);
    }
}

extern "C" void kernel_launch(void* const* d_in, const int* in_sizes, int n_in,
                              void* d_out, int out_size) {
    const float* ctrl    = (const float*)d_in[0];
    const float* pw      = (const float*)d_in[1];
    const float* mem     = (const float*)d_in[2];
    const float* key_w   = (const float*)d_in[3];
    const float* key_b   = (const float*)d_in[4];
    const float* beta_w  = (const float*)d_in[5];
    const float* beta_b  = (const float*)d_in[6];
    const float* gate_w  = (const float*)d_in[7];
    const float* gate_b  = (const float*)d_in[8];
    const float* shift_w = (const float*)d_in[9];
    const float* shift_b = (const float*)d_in[10];
    const float* gamma_w = (const float*)d_in[11];
    const float* gamma_b = (const float*)d_in[12];
    // d_in[13..16] = erase_w/b, add_w/b — unused by the output, skipped.
    float* out = (float*)d_out;
    float* out_read = out + (size_t)BB * NN;

    k_init<<<32, 256>>>(out_read);
    k_proj<<<BB, 512>>>(ctrl, key_w, key_b, beta_w, beta_b, gate_w, gate_b,
                        shift_w, shift_b, gamma_w, gamma_b);
    k_sim<<<dim3(NN / 256, BB), 256>>>(mem);
    k_w<<<dim3(NN / 1024, BB), 256>>>(pw, out);
    k_read<<<dim3(NN / 256, BB), 256>>>(mem, out);
}

// round 6
// speedup vs baseline: 2.7670x; 1.0306x over previous
#include <cuda_runtime.h>
#include <math.h>

#define BB 64
#define NN 16384
#define MM 128
#define CC 1024
#define EPSV 1e-16f

// ---- scratch (device globals; no allocation allowed) ----
__device__ float g_S[BB * NN];          // 4 MB: exp(beta*(sim-1))
__device__ float g_k[BB * MM];
__device__ float g_kn[BB];
__device__ float g_beta[BB], g_gate[BB], g_gamma[BB];
__device__ float g_shift[BB][3];
__device__ float g_Z[BB];               // softmax denominator (shift = beta)
__device__ float g_WZ[BB];              // sharpen denominator

__device__ __forceinline__ float softplus_f(float x) {
    return (x > 20.f) ? x : log1pf(expf(x));
}

// ---- 1. projections (one block per batch) + init duties ----
__global__ void __launch_bounds__(512) k_proj(
        const float* __restrict__ ctrl,
        const float* __restrict__ key_w, const float* __restrict__ key_b,
        const float* __restrict__ beta_w, const float* __restrict__ beta_b,
        const float* __restrict__ gate_w, const float* __restrict__ gate_b,
        const float* __restrict__ shift_w, const float* __restrict__ shift_b,
        const float* __restrict__ gamma_w, const float* __restrict__ gamma_b,
        float* __restrict__ out_read) {
    __shared__ float sc[CC];
    __shared__ float kred[4][MM];
    __shared__ float r6[6][16];
    __shared__ float red[MM];
    int b = blockIdx.x, t = threadIdx.x;
    int lane = t & 31, wid = t >> 5;

    // init duties: zero accumulators + this batch's read_vec slice
    if (t < MM) out_read[b * MM + t] = 0.f;
    if (t == 0) { g_Z[b] = 0.f; g_WZ[b] = 0.f; }

    for (int i = t; i < CC; i += 512) sc[i] = ctrl[b * CC + i];
    __syncthreads();

    // key column (t&127), C-quarter (t>>7)
    int q = t >> 7, col = t & 127;
    float acc = 0.f;
    int c0 = q * 256;
    #pragma unroll 8
    for (int c = c0; c < c0 + 256; c++) acc += sc[c] * key_w[c * MM + col];
    kred[q][col] = acc;

    // 6 scalar dots, warp-reduce
    float a0 = 0, a1 = 0, a2 = 0, s0 = 0, s1 = 0, s2 = 0;
    for (int c = t; c < CC; c += 512) {
        float x = sc[c];
        a0 += x * beta_w[c];
        a1 += x * gate_w[c];
        a2 += x * gamma_w[c];
        s0 += x * shift_w[c * 3 + 0];
        s1 += x * shift_w[c * 3 + 1];
        s2 += x * shift_w[c * 3 + 2];
    }
    #pragma unroll
    for (int off = 16; off > 0; off >>= 1) {
        a0 += __shfl_down_sync(0xffffffffu, a0, off);
        a1 += __shfl_down_sync(0xffffffffu, a1, off);
        a2 += __shfl_down_sync(0xffffffffu, a2, off);
        s0 += __shfl_down_sync(0xffffffffu, s0, off);
        s1 += __shfl_down_sync(0xffffffffu, s1, off);
        s2 += __shfl_down_sync(0xffffffffu, s2, off);
    }
    if (lane == 0) {
        r6[0][wid] = a0; r6[1][wid] = a1; r6[2][wid] = a2;
        r6[3][wid] = s0; r6[4][wid] = s1; r6[5][wid] = s2;
    }
    __syncthreads();

    if (t < MM) {
        float kt = tanhf(kred[0][t] + kred[1][t] + kred[2][t] + kred[3][t] + key_b[t]);
        g_k[b * MM + t] = kt;
        red[t] = kt * kt;
    }
    __syncthreads();
    for (int s = 64; s > 0; s >>= 1) {
        if (t < s) red[t] += red[t + s];
        __syncthreads();
    }
    if (t == 0) {
        g_kn[b] = sqrtf(red[0]);
        float v[6];
        #pragma unroll
        for (int j = 0; j < 6; j++) {
            float sum = 0.f;
            #pragma unroll
            for (int w = 0; w < 16; w++) sum += r6[j][w];
            v[j] = sum;
        }
        g_beta[b]  = softplus_f(v[0] + beta_b[0]);
        g_gate[b]  = 1.f / (1.f + expf(-(v[1] + gate_b[0])));
        g_gamma[b] = 1.f + softplus_f(v[2] + gamma_b[0]);
        float v0 = v[3] + shift_b[0];
        float v1 = v[4] + shift_b[1];
        float v2 = v[5] + shift_b[2];
        float mx = fmaxf(v0, fmaxf(v1, v2));
        float e0 = expf(v0 - mx), e1 = expf(v1 - mx), e2 = expf(v2 - mx);
        float inv = 1.f / (e0 + e1 + e2);
        g_shift[b][0] = e0 * inv;
        g_shift[b][1] = e1 * inv;
        g_shift[b][2] = e2 * inv;
    }
}

// ---- 2. pass 1 over memory: exp(beta*(sim-1)) + Z ----
__global__ void __launch_bounds__(256) k_sim(const float* __restrict__ mem) {
    int b = blockIdx.y;
    int tid = threadIdx.x, warp = tid >> 5, lane = tid & 31;
    int sub = lane & 7, rg = lane >> 3;
    __shared__ float sk[MM];
    if (tid < MM) sk[tid] = g_k[b * MM + tid];
    __syncthreads();
    const float4* skp = (const float4*)sk;
    float4 kq0 = skp[sub], kq1 = skp[sub + 8], kq2 = skp[sub + 16], kq3 = skp[sub + 24];
    float beta = g_beta[b], kn = g_kn[b];
    float zsum = 0.f;
    int base = blockIdx.x * 256 + warp * 32;
    const float4* mp = (const float4*)(mem + (size_t)b * NN * MM);

    #pragma unroll 4
    for (int j = 0; j < 8; j++) {
        int row = base + j * 4 + rg;
        const float4* rp = mp + (size_t)row * 32;
        float4 v0 = rp[sub], v1 = rp[sub + 8], v2 = rp[sub + 16], v3 = rp[sub + 24];
        float dot = v0.x * kq0.x + v0.y * kq0.y + v0.z * kq0.z + v0.w * kq0.w
                  + v1.x * kq1.x + v1.y * kq1.y + v1.z * kq1.z + v1.w * kq1.w
                  + v2.x * kq2.x + v2.y * kq2.y + v2.z * kq2.z + v2.w * kq2.w
                  + v3.x * kq3.x + v3.y * kq3.y + v3.z * kq3.z + v3.w * kq3.w;
        float nrm = v0.x * v0.x + v0.y * v0.y + v0.z * v0.z + v0.w * v0.w
                  + v1.x * v1.x + v1.y * v1.y + v1.z * v1.z + v1.w * v1.w
                  + v2.x * v2.x + v2.y * v2.y + v2.z * v2.z + v2.w * v2.w
                  + v3.x * v3.x + v3.y * v3.y + v3.z * v3.z + v3.w * v3.w;
        #pragma unroll
        for (int off = 4; off > 0; off >>= 1) {
            dot += __shfl_down_sync(0xffffffffu, dot, off);
            nrm += __shfl_down_sync(0xffffffffu, nrm, off);
        }
        if (sub == 0) {
            float s = beta * dot / (kn * sqrtf(nrm) + EPSV);
            float e = __expf(s - beta);
            g_S[b * NN + row] = e;
            zsum += e;
        }
    }
    zsum += __shfl_down_sync(0xffffffffu, zsum, 16);
    zsum += __shfl_down_sync(0xffffffffu, zsum, 8);
    if (lane == 0) atomicAdd(&g_Z[b], zsum);
}

// ---- 3. fused: gated interp + shift + sharpen (unnormalized) + weighted read ----
__global__ void __launch_bounds__(256) k_wread(const float* __restrict__ mem,
                                               const float* __restrict__ pw,
                                               float* __restrict__ out) {
    __shared__ float sw[256];
    __shared__ float4 sacc[256];
    __shared__ float swz[8];
    int b = blockIdx.y, t = threadIdx.x, warp = t >> 5, lane = t & 31;
    int base = blockIdx.x * 256;

    // --- compute unnormalized sharpened weight wp for slot base+t ---
    float gate = g_gate[b], og = 1.f - gate;
    float invZ = 1.f / g_Z[b];
    float s0 = g_shift[b][0], s1 = g_shift[b][1], s2 = g_shift[b][2];
    float gamma = g_gamma[b];
    const float* Sb = g_S + (size_t)b * NN;
    const float* pwb = pw + (size_t)b * NN;
    int n = base + t;
    int nm = (n - 1) & (NN - 1), np = (n + 1) & (NN - 1);
    float wm = gate * Sb[nm] * invZ + og * pwb[nm];
    float wc = gate * Sb[n]  * invZ + og * pwb[n];
    float wl = gate * Sb[np] * invZ + og * pwb[np];
    float ws = s0 * wm + s1 * wc + s2 * wl;
    float wp = __powf(ws, gamma);
    out[(size_t)b * NN + n] = wp;     // unnormalized; k_fix scales by 1/WZ
    sw[t] = wp;

    // WZ partial: warp reduce, then block reduce via shared
    float z = wp;
    #pragma unroll
    for (int off = 16; off > 0; off >>= 1) z += __shfl_down_sync(0xffffffffu, z, off);
    if (lane == 0) swz[warp] = z;
    __syncthreads();
    if (t == 0) {
        float s = swz[0];
        #pragma unroll
        for (int w8 = 1; w8 < 8; w8++) s += swz[w8];
        atomicAdd(&g_WZ[b], s);
    }

    // --- weighted read with unnormalized wp ---
    const float4* mp = (const float4*)(mem + ((size_t)b * NN + base + warp * 32) * MM);
    const float* swp = sw + warp * 32;
    float4 acc = make_float4(0.f, 0.f, 0.f, 0.f);
    #pragma unroll 4
    for (int i = 0; i < 32; i++) {
        float4 v = mp[(size_t)i * 32 + lane];
        float wi = swp[i];
        acc.x += wi * v.x; acc.y += wi * v.y;
        acc.z += wi * v.z; acc.w += wi * v.w;
    }
    sacc[t] = acc;
    __syncthreads();

    if (t < 32) {
        float4 s = sacc[t];
        #pragma unroll
        for (int w8 = 1; w8 < 8; w8++) {
            float4 o = sacc[w8 * 32 + t];
            s.x += o.x; s.y += o.y; s.z += o.z; s.w += o.w;
        }
        float* rd = out + (size_t)BB * NN + b * MM + t * 4;
        atomicAdd(rd + 0, s.x);
        atomicAdd(rd + 1, s.y);
        atomicAdd(rd + 2, s.z);
        atomicAdd(rd + 3, s.w);
    }
}

// ---- 4. epilogue: scale weights and read_vec by 1/WZ ----
__global__ void __launch_bounds__(256) k_fix(float* __restrict__ out) {
    int b = blockIdx.y, t = threadIdx.x;
    float inv = 1.f / (g_WZ[b] + EPSV);
    float4* wb = (float4*)(out + (size_t)b * NN);
    int idx = blockIdx.x * 256 + t;
    float4 v = wb[idx];
    v.x *= inv; v.y *= inv; v.z *= inv; v.w *= inv;
    wb[idx] = v;
    if (blockIdx.x == 0 && t < MM) {
        out[(size_t)BB * NN + b * MM + t] *= inv;
    }
}

extern "C" void kernel_launch(void* const* d_in, const int* in_sizes, int n_in,
                              void* d_out, int out_size) {
    const float* ctrl    = (const float*)d_in[0];
    const float* pw      = (const float*)d_in[1];
    const float* mem     = (const float*)d_in[2];
    const float* key_w   = (const float*)d_in[3];
    const float* key_b   = (const float*)d_in[4];
    const float* beta_w  = (const float*)d_in[5];
    const float* beta_b  = (const float*)d_in[6];
    const float* gate_w  = (const float*)d_in[7];
    const float* gate_b  = (const float*)d_in[8];
    const float* shift_w = (const float*)d_in[9];
    const float* shift_b = (const float*)d_in[10];
    const float* gamma_w = (const float*)d_in[11];
    const float* gamma_b = (const float*)d_in[12];
    // d_in[13..16] = erase_w/b, add_w/b — unused by the output, skipped.
    float* out = (float*)d_out;
    float* out_read = out + (size_t)BB * NN;

    k_proj<<<BB, 512>>>(ctrl, key_w, key_b, beta_w, beta_b, gate_w, gate_b,
                        shift_w, shift_b, gamma_w, gamma_b, out_read);
    k_sim<<<dim3(NN / 256, BB), 256>>>(mem);
    k_wread<<<dim3(NN / 256, BB), 256>>>(mem, pw, out);
    k_fix<<<dim3(NN / 1024, BB), 256>>>(out);
}

// round 7
// speedup vs baseline: 2.8379x; 1.0256x over previous
#include <cuda_runtime.h>
#include <math.h>

#define BB 64
#define NN 16384
#define MM 128
#define CC 1024
#define EPSV 1e-16f
#define SIMB (BB * 64)   // 4096 sim blocks

// ---- scratch (device globals; no allocation allowed) ----
__device__ float g_S[BB * NN];          // 4 MB: exp(beta*(sim-1))
__device__ float g_k[BB * MM];
__device__ float g_kn[BB];
__device__ float g_beta[BB], g_gate[BB], g_gamma[BB];
__device__ float g_shift[BB][3];
__device__ float g_Z[BB];               // softmax denominator (shift = beta)
__device__ float g_WZ[BB];              // sharpen denominator
__device__ unsigned int g_simctr[BB];   // sim blocks completed per batch
__device__ unsigned int g_wctr[BB];     // wread blocks completed per batch

__device__ __forceinline__ float softplus_f(float x) {
    return (x > 20.f) ? x : log1pf(expf(x));
}

// ---- 1. projections (one block per batch) + init duties ----
__global__ void __launch_bounds__(512) k_proj(
        const float* __restrict__ ctrl,
        const float* __restrict__ key_w, const float* __restrict__ key_b,
        const float* __restrict__ beta_w, const float* __restrict__ beta_b,
        const float* __restrict__ gate_w, const float* __restrict__ gate_b,
        const float* __restrict__ shift_w, const float* __restrict__ shift_b,
        const float* __restrict__ gamma_w, const float* __restrict__ gamma_b,
        float* __restrict__ out_read) {
    __shared__ float sc[CC];
    __shared__ float kred[4][MM];
    __shared__ float r6[6][16];
    __shared__ float red[MM];
    int b = blockIdx.x, t = threadIdx.x;
    int lane = t & 31, wid = t >> 5;

    // init duties: zero accumulators, counters, this batch's read_vec slice
    if (t < MM) out_read[b * MM + t] = 0.f;
    if (t == 0) { g_Z[b] = 0.f; g_WZ[b] = 0.f; g_simctr[b] = 0u; g_wctr[b] = 0u; }

    for (int i = t; i < CC; i += 512) sc[i] = ctrl[b * CC + i];
    __syncthreads();

    // key column (t&127), C-quarter (t>>7)
    int q = t >> 7, col = t & 127;
    float acc = 0.f;
    int c0 = q * 256;
    #pragma unroll 8
    for (int c = c0; c < c0 + 256; c++) acc += sc[c] * key_w[c * MM + col];
    kred[q][col] = acc;

    // 6 scalar dots, warp-reduce
    float a0 = 0, a1 = 0, a2 = 0, s0 = 0, s1 = 0, s2 = 0;
    for (int c = t; c < CC; c += 512) {
        float x = sc[c];
        a0 += x * beta_w[c];
        a1 += x * gate_w[c];
        a2 += x * gamma_w[c];
        s0 += x * shift_w[c * 3 + 0];
        s1 += x * shift_w[c * 3 + 1];
        s2 += x * shift_w[c * 3 + 2];
    }
    #pragma unroll
    for (int off = 16; off > 0; off >>= 1) {
        a0 += __shfl_down_sync(0xffffffffu, a0, off);
        a1 += __shfl_down_sync(0xffffffffu, a1, off);
        a2 += __shfl_down_sync(0xffffffffu, a2, off);
        s0 += __shfl_down_sync(0xffffffffu, s0, off);
        s1 += __shfl_down_sync(0xffffffffu, s1, off);
        s2 += __shfl_down_sync(0xffffffffu, s2, off);
    }
    if (lane == 0) {
        r6[0][wid] = a0; r6[1][wid] = a1; r6[2][wid] = a2;
        r6[3][wid] = s0; r6[4][wid] = s1; r6[5][wid] = s2;
    }
    __syncthreads();

    if (t < MM) {
        float kt = tanhf(kred[0][t] + kred[1][t] + kred[2][t] + kred[3][t] + key_b[t]);
        g_k[b * MM + t] = kt;
        red[t] = kt * kt;
    }
    __syncthreads();
    for (int s = 64; s > 0; s >>= 1) {
        if (t < s) red[t] += red[t + s];
        __syncthreads();
    }
    if (t == 0) {
        g_kn[b] = sqrtf(red[0]);
        float v[6];
        #pragma unroll
        for (int j = 0; j < 6; j++) {
            float sum = 0.f;
            #pragma unroll
            for (int w = 0; w < 16; w++) sum += r6[j][w];
            v[j] = sum;
        }
        g_beta[b]  = softplus_f(v[0] + beta_b[0]);
        g_gate[b]  = 1.f / (1.f + expf(-(v[1] + gate_b[0])));
        g_gamma[b] = 1.f + softplus_f(v[2] + gamma_b[0]);
        float v0 = v[3] + shift_b[0];
        float v1 = v[4] + shift_b[1];
        float v2 = v[5] + shift_b[2];
        float mx = fmaxf(v0, fmaxf(v1, v2));
        float e0 = expf(v0 - mx), e1 = expf(v1 - mx), e2 = expf(v2 - mx);
        float inv = 1.f / (e0 + e1 + e2);
        g_shift[b][0] = e0 * inv;
        g_shift[b][1] = e1 * inv;
        g_shift[b][2] = e2 * inv;
    }
}

// ---- 2. mega-kernel: sim blocks [0,4096), wread blocks [4096,8192) ----
__global__ void __launch_bounds__(256) k_main(const float* __restrict__ mem,
                                              const float* __restrict__ pw,
                                              float* __restrict__ out) {
    __shared__ float sh[256];
    __shared__ float4 sacc[256];
    __shared__ float swz[8];
    __shared__ unsigned int s_tick;
    int bid = blockIdx.x;
    int t = threadIdx.x, warp = t >> 5, lane = t & 31;

    if (bid < SIMB) {
        // ================= SIM role =================
        int b = bid >> 6;
        int base = (bid & 63) * 256 + warp * 32;
        int sub = lane & 7, rg = lane >> 3;
        if (t < MM) sh[t] = g_k[b * MM + t];
        __syncthreads();
        const float4* skp = (const float4*)sh;
        float4 kq0 = skp[sub], kq1 = skp[sub + 8], kq2 = skp[sub + 16], kq3 = skp[sub + 24];
        float beta = g_beta[b], kn = g_kn[b];
        float zsum = 0.f;
        const float4* mp = (const float4*)(mem + (size_t)b * NN * MM);

        #pragma unroll 4
        for (int j = 0; j < 8; j++) {
            int row = base + j * 4 + rg;
            const float4* rp = mp + (size_t)row * 32;
            float4 v0 = __ldcs(rp + sub),      v1 = __ldcs(rp + sub + 8);
            float4 v2 = __ldcs(rp + sub + 16), v3 = __ldcs(rp + sub + 24);
            float dot = v0.x * kq0.x + v0.y * kq0.y + v0.z * kq0.z + v0.w * kq0.w
                      + v1.x * kq1.x + v1.y * kq1.y + v1.z * kq1.z + v1.w * kq1.w
                      + v2.x * kq2.x + v2.y * kq2.y + v2.z * kq2.z + v2.w * kq2.w
                      + v3.x * kq3.x + v3.y * kq3.y + v3.z * kq3.z + v3.w * kq3.w;
            float nrm = v0.x * v0.x + v0.y * v0.y + v0.z * v0.z + v0.w * v0.w
                      + v1.x * v1.x + v1.y * v1.y + v1.z * v1.z + v1.w * v1.w
                      + v2.x * v2.x + v2.y * v2.y + v2.z * v2.z + v2.w * v2.w
                      + v3.x * v3.x + v3.y * v3.y + v3.z * v3.z + v3.w * v3.w;
            #pragma unroll
            for (int off = 4; off > 0; off >>= 1) {
                dot += __shfl_down_sync(0xffffffffu, dot, off);
                nrm += __shfl_down_sync(0xffffffffu, nrm, off);
            }
            if (sub == 0) {
                float s = beta * dot / (kn * sqrtf(nrm) + EPSV);
                float e = __expf(s - beta);
                g_S[b * NN + row] = e;
                zsum += e;
            }
        }
        zsum += __shfl_down_sync(0xffffffffu, zsum, 16);
        zsum += __shfl_down_sync(0xffffffffu, zsum, 8);
        if (lane == 0) atomicAdd(&g_Z[b], zsum);
        __threadfence();
        __syncthreads();
        if (t == 0) atomicAdd(&g_simctr[b], 1u);
    } else {
        // ================= WREAD role =================
        int r = bid - SIMB;
        int b = r >> 6;
        int base = (r & 63) * 256;
        int n = base + t;
        int nm = (n - 1) & (NN - 1), np = (n + 1) & (NN - 1);
        const float* pwb = pw + (size_t)b * NN;
        // prefetch pw before spinning (independent of sim)
        float pm = __ldg(pwb + nm), pc = __ldg(pwb + n), pl = __ldg(pwb + np);

        // wait for sim(b) completion
        if (t == 0) {
            while (atomicAdd(&g_simctr[b], 0u) < 64u) __nanosleep(128);
        }
        __syncthreads();
        __threadfence();

        float gate = g_gate[b], og = 1.f - gate;
        float invZ = 1.f / g_Z[b];
        float s0 = g_shift[b][0], s1 = g_shift[b][1], s2 = g_shift[b][2];
        float gamma = g_gamma[b];
        const float* Sb = g_S + (size_t)b * NN;
        float wm = gate * Sb[nm] * invZ + og * pm;
        float wc = gate * Sb[n]  * invZ + og * pc;
        float wl = gate * Sb[np] * invZ + og * pl;
        float ws = s0 * wm + s1 * wc + s2 * wl;
        float wp = __powf(ws, gamma);
        out[(size_t)b * NN + n] = wp;   // unnormalized; last block rescales
        sh[t] = wp;

        // WZ partial
        float z = wp;
        #pragma unroll
        for (int off = 16; off > 0; off >>= 1) z += __shfl_down_sync(0xffffffffu, z, off);
        if (lane == 0) swz[warp] = z;
        __syncthreads();
        if (t == 0) {
            float s = swz[0];
            #pragma unroll
            for (int w8 = 1; w8 < 8; w8++) s += swz[w8];
            atomicAdd(&g_WZ[b], s);
        }

        // weighted read with unnormalized wp
        const float4* mp = (const float4*)(mem + ((size_t)b * NN + base + warp * 32) * MM);
        const float* swp = sh + warp * 32;
        float4 acc = make_float4(0.f, 0.f, 0.f, 0.f);
        #pragma unroll 4
        for (int i = 0; i < 32; i++) {
            float4 v = __ldcs(mp + (size_t)i * 32 + lane);
            float wi = swp[i];
            acc.x += wi * v.x; acc.y += wi * v.y;
            acc.z += wi * v.z; acc.w += wi * v.w;
        }
        sacc[t] = acc;
        __syncthreads();
        if (t < 32) {
            float4 s = sacc[t];
            #pragma unroll
            for (int w8 = 1; w8 < 8; w8++) {
                float4 o = sacc[w8 * 32 + t];
                s.x += o.x; s.y += o.y; s.z += o.z; s.w += o.w;
            }
            float* rd = out + (size_t)BB * NN + b * MM + t * 4;
            atomicAdd(rd + 0, s.x);
            atomicAdd(rd + 1, s.y);
            atomicAdd(rd + 2, s.z);
            atomicAdd(rd + 3, s.w);
        }

        // ticket: last wread block of batch b normalizes weights + read_vec
        __threadfence();
        __syncthreads();
        if (t == 0) s_tick = atomicAdd(&g_wctr[b], 1u);
        __syncthreads();
        if (s_tick == 63u) {
            __threadfence();
            float inv = 1.f / (g_WZ[b] + EPSV);
            float4* wb = (float4*)(out + (size_t)b * NN);
            #pragma unroll 4
            for (int i = t; i < NN / 4; i += 256) {
                float4 v = wb[i];
                v.x *= inv; v.y *= inv; v.z *= inv; v.w *= inv;
                wb[i] = v;
            }
            if (t < 32) {
                float4* rv = (float4*)(out + (size_t)BB * NN + b * MM);
                float4 v = rv[t];
                v.x *= inv; v.y *= inv; v.z *= inv; v.w *= inv;
                rv[t] = v;
            }
        }
    }
}

extern "C" void kernel_launch(void* const* d_in, const int* in_sizes, int n_in,
                              void* d_out, int out_size) {
    const float* ctrl    = (const float*)d_in[0];
    const float* pw      = (const float*)d_in[1];
    const float* mem     = (const float*)d_in[2];
    const float* key_w   = (const float*)d_in[3];
    const float* key_b   = (const float*)d_in[4];
    const float* beta_w  = (const float*)d_in[5];
    const float* beta_b  = (const float*)d_in[6];
    const float* gate_w  = (const float*)d_in[7];
    const float* gate_b  = (const float*)d_in[8];
    const float* shift_w = (const float*)d_in[9];
    const float* shift_b = (const float*)d_in[10];
    const float* gamma_w = (const float*)d_in[11];
    const float* gamma_b = (const float*)d_in[12];
    // d_in[13..16] = erase_w/b, add_w/b — unused by the output, skipped.
    float* out = (float*)d_out;
    float* out_read = out + (size_t)BB * NN;

    k_proj<<<BB, 512>>>(ctrl, key_w, key_b, beta_w, beta_b, gate_w, gate_b,
                        shift_w, shift_b, gamma_w, gamma_b, out_read);
    k_main<<<2 * SIMB, 256>>>(mem, pw, out);
}

// round 12
// speedup vs baseline: 3.3325x; 1.1743x over previous
#include <cuda_runtime.h>
#include <math.h>

#define BB 64
#define NN 16384
#define MM 128
#define CC 1024
#define EPSV 1e-16f
#define LAG 8                     // wread trails sim by LAG batches (64 MB < L2)
#define NGROUP (BB + LAG)         // 72 groups of 128 bids

// ---- scratch (device globals; no allocation allowed) ----
__device__ float g_S[BB * NN];          // 4 MB: exp(beta*(sim-1))
__device__ float g_k[BB * MM];
__device__ float g_kn[BB];
__device__ float g_beta[BB], g_gate[BB], g_gamma[BB];
__device__ float g_shift[BB][3];
__device__ float g_Z[BB];               // softmax denominator (shift = beta)
__device__ float g_WZ[BB];              // sharpen denominator
__device__ unsigned int g_simctr[BB];   // sim blocks completed per batch
__device__ unsigned int g_wctr[BB];     // wread blocks completed per batch

__device__ __forceinline__ float softplus_f(float x) {
    return (x > 20.f) ? x : log1pf(expf(x));
}

// ---- 1. projections (one block per batch) + init duties ----
__global__ void __launch_bounds__(512) k_proj(
        const float* __restrict__ ctrl,
        const float* __restrict__ key_w, const float* __restrict__ key_b,
        const float* __restrict__ beta_w, const float* __restrict__ beta_b,
        const float* __restrict__ gate_w, const float* __restrict__ gate_b,
        const float* __restrict__ shift_w, const float* __restrict__ shift_b,
        const float* __restrict__ gamma_w, const float* __restrict__ gamma_b,
        float* __restrict__ out_read) {
    __shared__ float sc[CC];
    __shared__ float kred[4][MM];
    __shared__ float r6[6][16];
    __shared__ float red[MM];
    int b = blockIdx.x, t = threadIdx.x;
    int lane = t & 31, wid = t >> 5;

    if (t < MM) out_read[b * MM + t] = 0.f;
    if (t == 0) { g_Z[b] = 0.f; g_WZ[b] = 0.f; g_simctr[b] = 0u; g_wctr[b] = 0u; }

    for (int i = t; i < CC; i += 512) sc[i] = ctrl[b * CC + i];
    __syncthreads();

    int q = t >> 7, col = t & 127;
    float acc = 0.f;
    int c0 = q * 256;
    #pragma unroll 8
    for (int c = c0; c < c0 + 256; c++) acc += sc[c] * key_w[c * MM + col];
    kred[q][col] = acc;

    float a0 = 0, a1 = 0, a2 = 0, s0 = 0, s1 = 0, s2 = 0;
    for (int c = t; c < CC; c += 512) {
        float x = sc[c];
        a0 += x * beta_w[c];
        a1 += x * gate_w[c];
        a2 += x * gamma_w[c];
        s0 += x * shift_w[c * 3 + 0];
        s1 += x * shift_w[c * 3 + 1];
        s2 += x * shift_w[c * 3 + 2];
    }
    #pragma unroll
    for (int off = 16; off > 0; off >>= 1) {
        a0 += __shfl_down_sync(0xffffffffu, a0, off);
        a1 += __shfl_down_sync(0xffffffffu, a1, off);
        a2 += __shfl_down_sync(0xffffffffu, a2, off);
        s0 += __shfl_down_sync(0xffffffffu, s0, off);
        s1 += __shfl_down_sync(0xffffffffu, s1, off);
        s2 += __shfl_down_sync(0xffffffffu, s2, off);
    }
    if (lane == 0) {
        r6[0][wid] = a0; r6[1][wid] = a1; r6[2][wid] = a2;
        r6[3][wid] = s0; r6[4][wid] = s1; r6[5][wid] = s2;
    }
    __syncthreads();

    if (t < MM) {
        float kt = tanhf(kred[0][t] + kred[1][t] + kred[2][t] + kred[3][t] + key_b[t]);
        g_k[b * MM + t] = kt;
        red[t] = kt * kt;
    }
    __syncthreads();
    for (int s = 64; s > 0; s >>= 1) {
        if (t < s) red[t] += red[t + s];
        __syncthreads();
    }
    if (t == 0) {
        g_kn[b] = sqrtf(red[0]);
        float v[6];
        #pragma unroll
        for (int j = 0; j < 6; j++) {
            float sum = 0.f;
            #pragma unroll
            for (int w = 0; w < 16; w++) sum += r6[j][w];
            v[j] = sum;
        }
        g_beta[b]  = softplus_f(v[0] + beta_b[0]);
        g_gate[b]  = 1.f / (1.f + expf(-(v[1] + gate_b[0])));
        g_gamma[b] = 1.f + softplus_f(v[2] + gamma_b[0]);
        float v0 = v[3] + shift_b[0];
        float v1 = v[4] + shift_b[1];
        float v2 = v[5] + shift_b[2];
        float mx = fmaxf(v0, fmaxf(v1, v2));
        float e0 = expf(v0 - mx), e1 = expf(v1 - mx), e2 = expf(v2 - mx);
        float inv = 1.f / (e0 + e1 + e2);
        g_shift[b][0] = e0 * inv;
        g_shift[b][1] = e1 * inv;
        g_shift[b][2] = e2 * inv;
    }
}

// ---- 2. mega-kernel: group g = [64 sim blocks of batch g | 64 wread of batch g-LAG] ----
__global__ void __launch_bounds__(256) k_main(const float* __restrict__ mem,
                                              const float* __restrict__ pw,
                                              float* __restrict__ out) {
    __shared__ float sh[256];
    __shared__ float4 sacc[256];
    __shared__ float swz[8];
    __shared__ unsigned int s_tick;
    int g = blockIdx.x >> 7, h = blockIdx.x & 127;
    int t = threadIdx.x, warp = t >> 5, lane = t & 31;

    if (h < 64) {
        // ================= SIM role: batch g, chunk h =================
        int b = g;
        if (b >= BB) return;
        int base = h * 256 + warp * 32;
        int sub = lane & 7, rg = lane >> 3;
        if (t < MM) sh[t] = g_k[b * MM + t];
        __syncthreads();
        const float4* skp = (const float4*)sh;
        float4 kq0 = skp[sub], kq1 = skp[sub + 8], kq2 = skp[sub + 16], kq3 = skp[sub + 24];
        float beta = g_beta[b], kn = g_kn[b];
        float zsum = 0.f;
        const float4* mp = (const float4*)(mem + (size_t)b * NN * MM);

        #pragma unroll 4
        for (int j = 0; j < 8; j++) {
            int row = base + j * 4 + rg;
            const float4* rp = mp + (size_t)row * 32;
            // default (cached) loads: keep this data resident in L2 for wread
            float4 v0 = __ldg(rp + sub),      v1 = __ldg(rp + sub + 8);
            float4 v2 = __ldg(rp + sub + 16), v3 = __ldg(rp + sub + 24);
            float dot = v0.x * kq0.x + v0.y * kq0.y + v0.z * kq0.z + v0.w * kq0.w
                      + v1.x * kq1.x + v1.y * kq1.y + v1.z * kq1.z + v1.w * kq1.w
                      + v2.x * kq2.x + v2.y * kq2.y + v2.z * kq2.z + v2.w * kq2.w
                      + v3.x * kq3.x + v3.y * kq3.y + v3.z * kq3.z + v3.w * kq3.w;
            float nrm = v0.x * v0.x + v0.y * v0.y + v0.z * v0.z + v0.w * v0.w
                      + v1.x * v1.x + v1.y * v1.y + v1.z * v1.z + v1.w * v1.w
                      + v2.x * v2.x + v2.y * v2.y + v2.z * v2.z + v2.w * v2.w
                      + v3.x * v3.x + v3.y * v3.y + v3.z * v3.z + v3.w * v3.w;
            #pragma unroll
            for (int off = 4; off > 0; off >>= 1) {
                dot += __shfl_down_sync(0xffffffffu, dot, off);
                nrm += __shfl_down_sync(0xffffffffu, nrm, off);
            }
            if (sub == 0) {
                float s = beta * dot / (kn * sqrtf(nrm) + EPSV);
                float e = __expf(s - beta);
                g_S[b * NN + row] = e;
                zsum += e;
            }
        }
        zsum += __shfl_down_sync(0xffffffffu, zsum, 16);
        zsum += __shfl_down_sync(0xffffffffu, zsum, 8);
        if (lane == 0) atomicAdd(&g_Z[b], zsum);
        __threadfence();
        __syncthreads();
        if (t == 0) atomicAdd(&g_simctr[b], 1u);
    } else {
        // ================= WREAD role: batch g-LAG, chunk h-64 =================
        int b = g - LAG;
        if (b < 0 || b >= BB) return;
        int base = (h - 64) * 256;
        int n = base + t;
        int nm = (n - 1) & (NN - 1), np = (n + 1) & (NN - 1);
        const float* pwb = pw + (size_t)b * NN;
        float pm = __ldg(pwb + nm), pc = __ldg(pwb + n), pl = __ldg(pwb + np);

        // wait for sim(b) completion (normally already done: ~2 waves behind)
        if (t == 0) {
            while (atomicAdd(&g_simctr[b], 0u) < 64u) __nanosleep(64);
        }
        __syncthreads();
        __threadfence();

        float gate = g_gate[b], og = 1.f - gate;
        float invZ = 1.f / g_Z[b];
        float s0 = g_shift[b][0], s1 = g_shift[b][1], s2 = g_shift[b][2];
        float gamma = g_gamma[b];
        const float* Sb = g_S + (size_t)b * NN;
        float wm = gate * Sb[nm] * invZ + og * pm;
        float wc = gate * Sb[n]  * invZ + og * pc;
        float wl = gate * Sb[np] * invZ + og * pl;
        float ws = s0 * wm + s1 * wc + s2 * wl;
        float wp = __powf(ws, gamma);
        out[(size_t)b * NN + n] = wp;   // unnormalized; last block rescales
        sh[t] = wp;

        float z = wp;
        #pragma unroll
        for (int off = 16; off > 0; off >>= 1) z += __shfl_down_sync(0xffffffffu, z, off);
        if (lane == 0) swz[warp] = z;
        __syncthreads();
        if (t == 0) {
            float s = swz[0];
            #pragma unroll
            for (int w8 = 1; w8 < 8; w8++) s += swz[w8];
            atomicAdd(&g_WZ[b], s);
        }

        // weighted read: expect L2 hits (data streamed by sim(b) LAG groups ago)
        const float4* mp = (const float4*)(mem + ((size_t)b * NN + base + warp * 32) * MM);
        const float* swp = sh + warp * 32;
        float4 acc = make_float4(0.f, 0.f, 0.f, 0.f);
        #pragma unroll 4
        for (int i = 0; i < 32; i++) {
            float4 v = __ldcs(mp + (size_t)i * 32 + lane);   // last use: evict-first
            float wi = swp[i];
            acc.x += wi * v.x; acc.y += wi * v.y;
            acc.z += wi * v.z; acc.w += wi * v.w;
        }
        sacc[t] = acc;
        __syncthreads();
        if (t < 32) {
            float4 s = sacc[t];
            #pragma unroll
            for (int w8 = 1; w8 < 8; w8++) {
                float4 o = sacc[w8 * 32 + t];
                s.x += o.x; s.y += o.y; s.z += o.z; s.w += o.w;
            }
            float* rd = out + (size_t)BB * NN + b * MM + t * 4;
            atomicAdd(rd + 0, s.x);
            atomicAdd(rd + 1, s.y);
            atomicAdd(rd + 2, s.z);
            atomicAdd(rd + 3, s.w);
        }

        // ticket: last wread block of batch b normalizes weights + read_vec
        __threadfence();
        __syncthreads();
        if (t == 0) s_tick = atomicAdd(&g_wctr[b], 1u);
        __syncthreads();
        if (s_tick == 63u) {
            __threadfence();
            float inv = 1.f / (g_WZ[b] + EPSV);
            float4* wb = (float4*)(out + (size_t)b * NN);
            #pragma unroll 4
            for (int i = t; i < NN / 4; i += 256) {
                float4 v = wb[i];
                v.x *= inv; v.y *= inv; v.z *= inv; v.w *= inv;
                wb[i] = v;
            }
            if (t < 32) {
                float4* rv = (float4*)(out + (size_t)BB * NN + b * MM);
                float4 v = rv[t];
                v.x *= inv; v.y *= inv; v.z *= inv; v.w *= inv;
                rv[t] = v;
            }
        }
    }
}

extern "C" void kernel_launch(void* const* d_in, const int* in_sizes, int n_in,
                              void* d_out, int out_size) {
    const float* ctrl    = (const float*)d_in[0];
    const float* pw      = (const float*)d_in[1];
    const float* mem     = (const float*)d_in[2];
    const float* key_w   = (const float*)d_in[3];
    const float* key_b   = (const float*)d_in[4];
    const float* beta_w  = (const float*)d_in[5];
    const float* beta_b  = (const float*)d_in[6];
    const float* gate_w  = (const float*)d_in[7];
    const float* gate_b  = (const float*)d_in[8];
    const float* shift_w = (const float*)d_in[9];
    const float* shift_b = (const float*)d_in[10];
    const float* gamma_w = (const float*)d_in[11];
    const float* gamma_b = (const float*)d_in[12];
    // d_in[13..16] = erase_w/b, add_w/b — unused by the output, skipped.
    float* out = (float*)d_out;
    float* out_read = out + (size_t)BB * NN;

    k_proj<<<BB, 512>>>(ctrl, key_w, key_b, beta_w, beta_b, gate_w, gate_b,
                        shift_w, shift_b, gamma_w, gamma_b, out_read);
    k_main<<<NGROUP * 128, 256>>>(mem, pw, out);
}